// round 6
// baseline (speedup 1.0000x reference)
#include <cuda_runtime.h>

// ---------------------------------------------------------------------------
// MetricPredictor: 2-layer GCN (degree features) + sum-pool + 2-layer MLP
// CSR-gather; 5 graph nodes: count, scan, fill(+pair-agg), agg2, h2sum+final.
// agg1 is computed with EXACT int atomics fused into the CSR fill pass.
// Cross-replay invariant: g_cnt is zero at kernel_launch entry
// (zero-initialized at load; re-zeroed by the last block of h2sum each call).
// ---------------------------------------------------------------------------

#define MAXN 16384
#define MAXE 524288
#define NTHREADS 256
#define FULLMASK 0xFFFFFFFFu
#define H2_GRID (MAXN / 32)   // 512 blocks

__device__ __align__(16) int   g_cnt[2 * MAXN];     // (in_deg, out_deg) interleaved
__device__ __align__(16) int   g_rowoff[MAXN + 1];
__device__ __align__(16) int   g_cursor[MAXN];
__device__ __align__(16) int   g_csrc[MAXE];
__device__ __align__(16) int   g_ai[2 * MAXN];      // agg1 pairs, exact int
__device__ __align__(16) float g_agg2[MAXN * 128];
__device__ __align__(16) float g_ge[256];
__device__ int g_done;

__device__ __forceinline__ int get_N(const int* np) {
    return np ? __ldg(np) : 10000;
}

// ---------------------------------------------------------------------------
// degree counts: 2 edges/thread, int2 loads, 4 independent REDG
__global__ void k_count(const int* __restrict__ src, const int* __restrict__ dst, int E) {
    int i = blockIdx.x * blockDim.x + threadIdx.x;
    int e0 = 2 * i;
    if (e0 + 1 < E) {
        int2 s = *(const int2*)&src[e0];
        int2 d = *(const int2*)&dst[e0];
        atomicAdd(&g_cnt[2 * d.x + 0], 1);
        atomicAdd(&g_cnt[2 * d.y + 0], 1);
        atomicAdd(&g_cnt[2 * s.x + 1], 1);
        atomicAdd(&g_cnt[2 * s.y + 1], 1);
    } else if (e0 < E) {
        atomicAdd(&g_cnt[2 * dst[e0] + 0], 1);
        atomicAdd(&g_cnt[2 * src[e0] + 1], 1);
    }
}

// exclusive scan of in-degrees -> g_rowoff, g_cursor; zero g_ai/g_ge/g_done
__global__ void __launch_bounds__(1024) k_scan() {
    __shared__ int s_part[1024];
    const int CH = MAXN / 1024;  // 16
    int t = threadIdx.x;
    int base = t * CH;
    int loc[CH];
    int sum = 0;
#pragma unroll
    for (int i = 0; i < CH; i++) { loc[i] = sum; sum += g_cnt[2 * (base + i)]; }
    s_part[t] = sum;
    __syncthreads();
    for (int off = 1; off < 1024; off <<= 1) {
        int v = (t >= off) ? s_part[t - off] : 0;
        __syncthreads();
        s_part[t] += v;
        __syncthreads();
    }
    int pre = (t > 0) ? s_part[t - 1] : 0;
#pragma unroll
    for (int i = 0; i < CH; i++) {
        int o = pre + loc[i];
        g_rowoff[base + i] = o;
        g_cursor[base + i] = o;
    }
    if (t == 1023) g_rowoff[MAXN] = s_part[1023];
    // zero the int agg1 accumulators (consumed by k_fill -> k_agg2 this call)
    for (int i = t; i < 2 * MAXN; i += 1024) g_ai[i] = 0;
    if (t < 256) g_ge[t] = 0.0f;
    if (t == 0) g_done = 0;
}

// fill CSR + fused pair aggregation:
//   pos = cursor[d]++ ; csrc[pos] = s ; g_ai[d] += (in_deg[s], out_deg[s])
// All three atomic chains are independent -> hides ATOMG latency.
__global__ void k_fill(const int* __restrict__ src, const int* __restrict__ dst, int E) {
    int e = blockIdx.x * blockDim.x + threadIdx.x;
    if (e >= E) return;
    int s = src[e], d = dst[e];
    int2 c = *(const int2*)&g_cnt[2 * s];   // (in_deg[s], out_deg[s]), 8B
    int pos = atomicAdd(&g_cursor[d], 1);
    g_csrc[pos] = s;
    atomicAdd(&g_ai[2 * d + 0], c.x);
    atomicAdd(&g_ai[2 * d + 1], c.y);
}

// agg2[d] = sum over in-neighbors s of relu(a0[s]*W1[0] + a1[s]*W1[1] + b1)
// One warp per node d; lane owns 4 columns (W1 cols in registers).
__global__ void k_agg2(const float* __restrict__ W1, const float* __restrict__ b1,
                       const int* __restrict__ np) {
    int N = get_N(np);
    int w = (blockIdx.x * blockDim.x + threadIdx.x) >> 5;
    if (w >= N) return;
    int lane = threadIdx.x & 31;
    int j = lane * 4;
    float4 w0 = *(const float4*)&W1[j];
    float4 w1 = *(const float4*)&W1[128 + j];
    float4 bb = *(const float4*)&b1[j];

    int beg = g_rowoff[w];
    int end = g_rowoff[w + 1];

    float4 acc0 = make_float4(0.f, 0.f, 0.f, 0.f);
    float4 acc1 = acc0, acc2 = acc0, acc3 = acc0;

    int k = beg;
    for (; k + 4 <= end; k += 4) {
        int s0 = __ldg(&g_csrc[k + 0]);
        int s1 = __ldg(&g_csrc[k + 1]);
        int s2 = __ldg(&g_csrc[k + 2]);
        int s3 = __ldg(&g_csrc[k + 3]);
        int2 q0 = *(const int2*)&g_ai[2 * s0];
        int2 q1 = *(const int2*)&g_ai[2 * s1];
        int2 q2 = *(const int2*)&g_ai[2 * s2];
        int2 q3 = *(const int2*)&g_ai[2 * s3];
        float2 p0 = make_float2((float)q0.x, (float)q0.y);
        float2 p1 = make_float2((float)q1.x, (float)q1.y);
        float2 p2 = make_float2((float)q2.x, (float)q2.y);
        float2 p3 = make_float2((float)q3.x, (float)q3.y);
        acc0.x += fmaxf(fmaf(p0.x, w0.x, fmaf(p0.y, w1.x, bb.x)), 0.f);
        acc0.y += fmaxf(fmaf(p0.x, w0.y, fmaf(p0.y, w1.y, bb.y)), 0.f);
        acc0.z += fmaxf(fmaf(p0.x, w0.z, fmaf(p0.y, w1.z, bb.z)), 0.f);
        acc0.w += fmaxf(fmaf(p0.x, w0.w, fmaf(p0.y, w1.w, bb.w)), 0.f);
        acc1.x += fmaxf(fmaf(p1.x, w0.x, fmaf(p1.y, w1.x, bb.x)), 0.f);
        acc1.y += fmaxf(fmaf(p1.x, w0.y, fmaf(p1.y, w1.y, bb.y)), 0.f);
        acc1.z += fmaxf(fmaf(p1.x, w0.z, fmaf(p1.y, w1.z, bb.z)), 0.f);
        acc1.w += fmaxf(fmaf(p1.x, w0.w, fmaf(p1.y, w1.w, bb.w)), 0.f);
        acc2.x += fmaxf(fmaf(p2.x, w0.x, fmaf(p2.y, w1.x, bb.x)), 0.f);
        acc2.y += fmaxf(fmaf(p2.x, w0.y, fmaf(p2.y, w1.y, bb.y)), 0.f);
        acc2.z += fmaxf(fmaf(p2.x, w0.z, fmaf(p2.y, w1.z, bb.z)), 0.f);
        acc2.w += fmaxf(fmaf(p2.x, w0.w, fmaf(p2.y, w1.w, bb.w)), 0.f);
        acc3.x += fmaxf(fmaf(p3.x, w0.x, fmaf(p3.y, w1.x, bb.x)), 0.f);
        acc3.y += fmaxf(fmaf(p3.x, w0.y, fmaf(p3.y, w1.y, bb.y)), 0.f);
        acc3.z += fmaxf(fmaf(p3.x, w0.z, fmaf(p3.y, w1.z, bb.z)), 0.f);
        acc3.w += fmaxf(fmaf(p3.x, w0.w, fmaf(p3.y, w1.w, bb.w)), 0.f);
    }
    for (; k < end; k++) {
        int s = __ldg(&g_csrc[k]);
        int2 q = *(const int2*)&g_ai[2 * s];
        float2 p = make_float2((float)q.x, (float)q.y);
        acc0.x += fmaxf(fmaf(p.x, w0.x, fmaf(p.y, w1.x, bb.x)), 0.f);
        acc0.y += fmaxf(fmaf(p.x, w0.y, fmaf(p.y, w1.y, bb.y)), 0.f);
        acc0.z += fmaxf(fmaf(p.x, w0.z, fmaf(p.y, w1.z, bb.z)), 0.f);
        acc0.w += fmaxf(fmaf(p.x, w0.w, fmaf(p.y, w1.w, bb.w)), 0.f);
    }
    float4 acc;
    acc.x = (acc0.x + acc1.x) + (acc2.x + acc3.x);
    acc.y = (acc0.y + acc1.y) + (acc2.y + acc3.y);
    acc.z = (acc0.z + acc1.z) + (acc2.z + acc3.z);
    acc.w = (acc0.w + acc1.w) + (acc2.w + acc3.w);
    *(float4*)&g_agg2[w * 128 + j] = acc;
}

// h2 = relu(agg2 @ W2 + b2); embedding accumulation; last block runs the
// final MLP and re-zeroes g_cnt for the next replay.
__global__ void __launch_bounds__(256) k_h2sum(const float* __restrict__ W2,
                                               const float* __restrict__ b2,
                                               const float* __restrict__ Wp1,
                                               const float* __restrict__ bp1,
                                               const float* __restrict__ Wp2,
                                               const float* __restrict__ bp2,
                                               float* __restrict__ out,
                                               const int* __restrict__ np) {
    int N = get_N(np);
    int base = blockIdx.x * 32;
    int t = threadIdx.x;

    __shared__ float s_a[32 * 128];
    __shared__ float s_ge[256];
    __shared__ int s_last;

    if (base < N) {
        s_ge[t] = 0.0f;
        for (int i = t; i < 32 * 128 / 4; i += 256) {
            int n = base + (i >> 5);
            float4 v = make_float4(0.f, 0.f, 0.f, 0.f);
            if (n < N) v = *(const float4*)&g_agg2[n * 128 + (i & 31) * 4];
            *(float4*)&s_a[i * 4] = v;
        }
        __syncthreads();

        int jg = t & 63;
        int mg = t >> 6;

        float acc[8][4];
#pragma unroll
        for (int m = 0; m < 8; m++)
#pragma unroll
            for (int c = 0; c < 4; c++) acc[m][c] = 0.0f;

        const float* sa = &s_a[mg * 8 * 128];
#pragma unroll 4
        for (int k = 0; k < 128; k++) {
            float4 wv = *(const float4*)&W2[k * 256 + jg * 4];
#pragma unroll
            for (int m = 0; m < 8; m++) {
                float a = sa[m * 128 + k];
                acc[m][0] = fmaf(a, wv.x, acc[m][0]);
                acc[m][1] = fmaf(a, wv.y, acc[m][1]);
                acc[m][2] = fmaf(a, wv.z, acc[m][2]);
                acc[m][3] = fmaf(a, wv.w, acc[m][3]);
            }
        }

        float4 bb = *(const float4*)&b2[jg * 4];
        float p0 = 0.f, p1 = 0.f, p2 = 0.f, p3 = 0.f;
#pragma unroll
        for (int m = 0; m < 8; m++) {
            if (base + mg * 8 + m < N) {
                p0 += fmaxf(acc[m][0] + bb.x, 0.0f);
                p1 += fmaxf(acc[m][1] + bb.y, 0.0f);
                p2 += fmaxf(acc[m][2] + bb.z, 0.0f);
                p3 += fmaxf(acc[m][3] + bb.w, 0.0f);
            }
        }
        atomicAdd(&s_ge[jg * 4 + 0], p0);
        atomicAdd(&s_ge[jg * 4 + 1], p1);
        atomicAdd(&s_ge[jg * 4 + 2], p2);
        atomicAdd(&s_ge[jg * 4 + 3], p3);
        __syncthreads();
        atomicAdd(&g_ge[t], s_ge[t]);
    }

    // ---- arrival counter ----
    __threadfence();
    if (t == 0) {
        int c = atomicAdd(&g_done, 1);
        s_last = (c == (int)gridDim.x - 1);
    }
    __syncthreads();
    if (!s_last) return;

    // ---- final MLP (single block) ----
    __shared__ float f_ge[256];
    __shared__ float f_m[128];
    float ge = g_ge[t];
    f_ge[t] = ge;
    out[t] = ge;
    __syncthreads();
    if (t < 128) {
        float acc = bp1[t];
        for (int k = 0; k < 256; k++)
            acc = fmaf(f_ge[k], __ldg(&Wp1[k * 128 + t]), acc);
        f_m[t] = fmaxf(acc, 0.0f) * __ldg(&Wp2[t]);
    }
    __syncthreads();
    for (int off = 64; off >= 1; off >>= 1) {
        if (t < off) f_m[t] += f_m[t + off];
        __syncthreads();
    }
    if (t == 0) out[256] = f_m[0] + bp2[0];

    // ---- re-zero degree counts for the next replay ----
    for (int i = t; i < 2 * MAXN; i += 256) g_cnt[i] = 0;
}

// ---------------------------------------------------------------------------
extern "C" void kernel_launch(void* const* d_in, const int* in_sizes, int n_in,
                              void* d_out, int out_size) {
    const float* W1  = (const float*)d_in[0];
    const float* b1  = (const float*)d_in[1];
    const float* W2  = (const float*)d_in[2];
    const float* b2  = (const float*)d_in[3];
    const float* Wp1 = (const float*)d_in[4];
    const float* bp1 = (const float*)d_in[5];
    const float* Wp2 = (const float*)d_in[6];
    const float* bp2 = (const float*)d_in[7];
    const int*   src = (const int*)d_in[8];
    const int*   dst = (const int*)d_in[9];
    const int*   np  = (n_in > 10) ? (const int*)d_in[10] : nullptr;
    int E = in_sizes[8];

    int eb  = (E + NTHREADS - 1) / NTHREADS;
    int eb2 = (E / 2 + NTHREADS - 1) / NTHREADS + 1;
    k_count<<<eb2, NTHREADS>>>(src, dst, E);
    k_scan<<<1, 1024>>>();
    k_fill<<<eb, NTHREADS>>>(src, dst, E);
    k_agg2<<<(MAXN * 32 + NTHREADS - 1) / NTHREADS, NTHREADS>>>(W1, b1, np);
    k_h2sum<<<H2_GRID, NTHREADS>>>(W2, b2, Wp1, bp1, Wp2, bp2, (float*)d_out, np);
    (void)out_size; (void)n_in;
}

// round 7
// speedup vs baseline: 1.0484x; 1.0484x over previous
#include <cuda_runtime.h>

// ---------------------------------------------------------------------------
// MetricPredictor: 2-layer GCN (degree features) + sum-pool + 2-layer MLP
// CSR-gather; 6 graph nodes: count, scan, fill, aggpair, agg2, h2sum+final.
// Round-7: float-pair degree table (aggpair), FFMA2-packed GEMM (h2sum).
// Cross-replay invariant: g_incnt/g_outcnt are zero at kernel_launch entry
// (zero-initialized at load; re-zeroed by the last block of h2sum each call).
// ---------------------------------------------------------------------------

#define MAXN 16384
#define MAXE 524288
#define NTHREADS 256
#define FULLMASK 0xFFFFFFFFu
#define H2_GRID (MAXN / 32)   // 512 blocks
#define TPAD 34               // transposed-tile row stride (even -> 8B aligned)

__device__ __align__(16) int   g_incnt[MAXN];
__device__ __align__(16) int   g_outcnt[MAXN];
__device__ __align__(16) int   g_rowoff[MAXN + 1];
__device__ __align__(16) int   g_cursor[MAXN];
__device__ __align__(16) int   g_csrc[MAXE];
__device__ __align__(16) float g_af[2 * MAXN];      // (in_deg, out_deg) as float2
__device__ __align__(16) float g_a[2 * MAXN];       // agg1 pairs (a0,a1)
__device__ __align__(16) float g_agg2[MAXN * 128];
__device__ __align__(16) float g_ge[256];
__device__ int g_done;

__device__ __forceinline__ int get_N(const int* np) {
    return np ? __ldg(np) : 10000;
}

__device__ __forceinline__ unsigned long long pack2(float x, float y) {
    unsigned long long r;
    asm("mov.b64 %0, {%1, %2};" : "=l"(r) : "f"(x), "f"(y));
    return r;
}
__device__ __forceinline__ unsigned long long fma2(unsigned long long a,
                                                   unsigned long long b,
                                                   unsigned long long c) {
    unsigned long long d;
    asm("fma.rn.f32x2 %0, %1, %2, %3;" : "=l"(d) : "l"(a), "l"(b), "l"(c));
    return d;
}
__device__ __forceinline__ void unpack2(unsigned long long v, float& lo, float& hi) {
    asm("mov.b64 {%0, %1}, %2;" : "=f"(lo), "=f"(hi) : "l"(v));
}

// ---------------------------------------------------------------------------
// degree counts: 2 edges/thread, int2 loads, 4 independent REDG
__global__ void k_count(const int* __restrict__ src, const int* __restrict__ dst, int E) {
    int i = blockIdx.x * blockDim.x + threadIdx.x;
    int e0 = 2 * i;
    if (e0 + 1 < E) {
        int2 s = *(const int2*)&src[e0];
        int2 d = *(const int2*)&dst[e0];
        atomicAdd(&g_incnt[d.x], 1);
        atomicAdd(&g_incnt[d.y], 1);
        atomicAdd(&g_outcnt[s.x], 1);
        atomicAdd(&g_outcnt[s.y], 1);
    } else if (e0 < E) {
        atomicAdd(&g_incnt[dst[e0]], 1);
        atomicAdd(&g_outcnt[src[e0]], 1);
    }
}

// exclusive scan of in-degrees -> g_rowoff, g_cursor; writes float-pair degree
// table g_af; zeroes g_ge/g_done.
__global__ void __launch_bounds__(1024) k_scan() {
    __shared__ int s_part[1024];
    const int CH = MAXN / 1024;  // 16
    int t = threadIdx.x;
    int base = t * CH;
    int loc[CH];
    int sum = 0;
#pragma unroll
    for (int i = 0; i < CH; i++) {
        int n = base + i;
        int ic = g_incnt[n];
        int oc = g_outcnt[n];
        loc[i] = sum;
        sum += ic;
        float2 f = make_float2((float)ic, (float)oc);
        *(float2*)&g_af[2 * n] = f;
    }
    s_part[t] = sum;
    __syncthreads();
    for (int off = 1; off < 1024; off <<= 1) {
        int v = (t >= off) ? s_part[t - off] : 0;
        __syncthreads();
        s_part[t] += v;
        __syncthreads();
    }
    int pre = (t > 0) ? s_part[t - 1] : 0;
#pragma unroll
    for (int i = 0; i < CH; i++) {
        int o = pre + loc[i];
        g_rowoff[base + i] = o;
        g_cursor[base + i] = o;
    }
    if (t == 1023) g_rowoff[MAXN] = s_part[1023];
    if (t < 256) g_ge[t] = 0.0f;
    if (t == 0) g_done = 0;
}

// fill CSR (1 edge/thread — measured-good shape)
__global__ void k_fill(const int* __restrict__ src, const int* __restrict__ dst, int E) {
    int e = blockIdx.x * blockDim.x + threadIdx.x;
    if (e >= E) return;
    int pos = atomicAdd(&g_cursor[dst[e]], 1);
    g_csrc[pos] = src[e];
}

// agg1 pairs: g_a[n] = sum over in-neighbors s of (in_deg[s], out_deg[s])
// One 8B float2 load per edge, no conversions.
__global__ void k_aggpair(const int* __restrict__ np) {
    int N = get_N(np);
    int w = (blockIdx.x * blockDim.x + threadIdx.x) >> 5;
    if (w >= N) return;
    int lane = threadIdx.x & 31;
    int beg = g_rowoff[w];
    int end = g_rowoff[w + 1];
    float a0 = 0.f, a1 = 0.f;
    for (int j = beg + lane; j < end; j += 32) {
        int s = g_csrc[j];
        float2 p = *(const float2*)&g_af[2 * s];
        a0 += p.x;
        a1 += p.y;
    }
#pragma unroll
    for (int off = 16; off >= 1; off >>= 1) {
        a0 += __shfl_down_sync(FULLMASK, a0, off);
        a1 += __shfl_down_sync(FULLMASK, a1, off);
    }
    if (lane == 0) {
        g_a[2 * w + 0] = a0;
        g_a[2 * w + 1] = a1;
    }
}

// agg2[d] = sum over in-neighbors s of relu(a0[s]*W1[0] + a1[s]*W1[1] + b1)
// One warp per node d; lane owns 4 columns (W1 cols in registers).
__global__ void k_agg2(const float* __restrict__ W1, const float* __restrict__ b1,
                       const int* __restrict__ np) {
    int N = get_N(np);
    int w = (blockIdx.x * blockDim.x + threadIdx.x) >> 5;
    if (w >= N) return;
    int lane = threadIdx.x & 31;
    int j = lane * 4;
    float4 w0 = *(const float4*)&W1[j];
    float4 w1 = *(const float4*)&W1[128 + j];
    float4 bb = *(const float4*)&b1[j];

    int beg = g_rowoff[w];
    int end = g_rowoff[w + 1];

    float4 acc0 = make_float4(0.f, 0.f, 0.f, 0.f);
    float4 acc1 = acc0, acc2 = acc0, acc3 = acc0;

    int k = beg;
    for (; k + 4 <= end; k += 4) {
        int s0 = __ldg(&g_csrc[k + 0]);
        int s1 = __ldg(&g_csrc[k + 1]);
        int s2 = __ldg(&g_csrc[k + 2]);
        int s3 = __ldg(&g_csrc[k + 3]);
        float2 p0 = *(const float2*)&g_a[2 * s0];
        float2 p1 = *(const float2*)&g_a[2 * s1];
        float2 p2 = *(const float2*)&g_a[2 * s2];
        float2 p3 = *(const float2*)&g_a[2 * s3];
        acc0.x += fmaxf(fmaf(p0.x, w0.x, fmaf(p0.y, w1.x, bb.x)), 0.f);
        acc0.y += fmaxf(fmaf(p0.x, w0.y, fmaf(p0.y, w1.y, bb.y)), 0.f);
        acc0.z += fmaxf(fmaf(p0.x, w0.z, fmaf(p0.y, w1.z, bb.z)), 0.f);
        acc0.w += fmaxf(fmaf(p0.x, w0.w, fmaf(p0.y, w1.w, bb.w)), 0.f);
        acc1.x += fmaxf(fmaf(p1.x, w0.x, fmaf(p1.y, w1.x, bb.x)), 0.f);
        acc1.y += fmaxf(fmaf(p1.x, w0.y, fmaf(p1.y, w1.y, bb.y)), 0.f);
        acc1.z += fmaxf(fmaf(p1.x, w0.z, fmaf(p1.y, w1.z, bb.z)), 0.f);
        acc1.w += fmaxf(fmaf(p1.x, w0.w, fmaf(p1.y, w1.w, bb.w)), 0.f);
        acc2.x += fmaxf(fmaf(p2.x, w0.x, fmaf(p2.y, w1.x, bb.x)), 0.f);
        acc2.y += fmaxf(fmaf(p2.x, w0.y, fmaf(p2.y, w1.y, bb.y)), 0.f);
        acc2.z += fmaxf(fmaf(p2.x, w0.z, fmaf(p2.y, w1.z, bb.z)), 0.f);
        acc2.w += fmaxf(fmaf(p2.x, w0.w, fmaf(p2.y, w1.w, bb.w)), 0.f);
        acc3.x += fmaxf(fmaf(p3.x, w0.x, fmaf(p3.y, w1.x, bb.x)), 0.f);
        acc3.y += fmaxf(fmaf(p3.x, w0.y, fmaf(p3.y, w1.y, bb.y)), 0.f);
        acc3.z += fmaxf(fmaf(p3.x, w0.z, fmaf(p3.y, w1.z, bb.z)), 0.f);
        acc3.w += fmaxf(fmaf(p3.x, w0.w, fmaf(p3.y, w1.w, bb.w)), 0.f);
    }
    for (; k < end; k++) {
        int s = __ldg(&g_csrc[k]);
        float2 p = *(const float2*)&g_a[2 * s];
        acc0.x += fmaxf(fmaf(p.x, w0.x, fmaf(p.y, w1.x, bb.x)), 0.f);
        acc0.y += fmaxf(fmaf(p.x, w0.y, fmaf(p.y, w1.y, bb.y)), 0.f);
        acc0.z += fmaxf(fmaf(p.x, w0.z, fmaf(p.y, w1.z, bb.z)), 0.f);
        acc0.w += fmaxf(fmaf(p.x, w0.w, fmaf(p.y, w1.w, bb.w)), 0.f);
    }
    float4 acc;
    acc.x = (acc0.x + acc1.x) + (acc2.x + acc3.x);
    acc.y = (acc0.y + acc1.y) + (acc2.y + acc3.y);
    acc.z = (acc0.z + acc1.z) + (acc2.z + acc3.z);
    acc.w = (acc0.w + acc1.w) + (acc2.w + acc3.w);
    *(float4*)&g_agg2[w * 128 + j] = acc;
}

// h2 = relu(agg2 @ W2 + b2) via packed FFMA2; embedding accumulation; last
// block runs the final MLP and re-zeroes the count arrays for the next replay.
// Block tile: 32 nodes x 256 cols; thread tile: 4 node-PAIRS x 4 cols.
__global__ void __launch_bounds__(256) k_h2sum(const float* __restrict__ W2,
                                               const float* __restrict__ b2,
                                               const float* __restrict__ Wp1,
                                               const float* __restrict__ bp1,
                                               const float* __restrict__ Wp2,
                                               const float* __restrict__ bp2,
                                               float* __restrict__ out,
                                               const int* __restrict__ np) {
    int N = get_N(np);
    int base = blockIdx.x * 32;
    int t = threadIdx.x;

    __shared__ float s_aT[128 * TPAD];   // transposed tile: [k][node]
    __shared__ float s_ge[256];
    __shared__ int s_last;

    if (base < N) {
        s_ge[t] = 0.0f;
        // transpose-load: warp reads one node's row coalesced, scatters to s_aT
        for (int i = t; i < 32 * 128 / 4; i += 256) {
            int n = i >> 5;          // 0..31 (node within tile)
            int kg = i & 31;         // 0..31 (k-quad)
            float4 v = make_float4(0.f, 0.f, 0.f, 0.f);
            if (base + n < N) v = *(const float4*)&g_agg2[(base + n) * 128 + kg * 4];
            s_aT[(kg * 4 + 0) * TPAD + n] = v.x;
            s_aT[(kg * 4 + 1) * TPAD + n] = v.y;
            s_aT[(kg * 4 + 2) * TPAD + n] = v.z;
            s_aT[(kg * 4 + 3) * TPAD + n] = v.w;
        }
        __syncthreads();

        int jg = t & 63;   // column group (4 cols)
        int mg = t >> 6;   // node group (8 nodes = 4 pairs)

        unsigned long long acc2[4][4];   // [pair][col]
#pragma unroll
        for (int p = 0; p < 4; p++)
#pragma unroll
            for (int c = 0; c < 4; c++) acc2[p][c] = 0ull;

        const float* rowp = &s_aT[mg * 8];
#pragma unroll 2
        for (int k = 0; k < 128; k++) {
            float4 wv = *(const float4*)&W2[k * 256 + jg * 4];
            unsigned long long wx = pack2(wv.x, wv.x);
            unsigned long long wy = pack2(wv.y, wv.y);
            unsigned long long wz = pack2(wv.z, wv.z);
            unsigned long long ww = pack2(wv.w, wv.w);
            unsigned long long a0 = *(const unsigned long long*)&rowp[0];
            unsigned long long a1 = *(const unsigned long long*)&rowp[2];
            unsigned long long a2 = *(const unsigned long long*)&rowp[4];
            unsigned long long a3 = *(const unsigned long long*)&rowp[6];
            acc2[0][0] = fma2(a0, wx, acc2[0][0]);
            acc2[0][1] = fma2(a0, wy, acc2[0][1]);
            acc2[0][2] = fma2(a0, wz, acc2[0][2]);
            acc2[0][3] = fma2(a0, ww, acc2[0][3]);
            acc2[1][0] = fma2(a1, wx, acc2[1][0]);
            acc2[1][1] = fma2(a1, wy, acc2[1][1]);
            acc2[1][2] = fma2(a1, wz, acc2[1][2]);
            acc2[1][3] = fma2(a1, ww, acc2[1][3]);
            acc2[2][0] = fma2(a2, wx, acc2[2][0]);
            acc2[2][1] = fma2(a2, wy, acc2[2][1]);
            acc2[2][2] = fma2(a2, wz, acc2[2][2]);
            acc2[2][3] = fma2(a2, ww, acc2[2][3]);
            acc2[3][0] = fma2(a3, wx, acc2[3][0]);
            acc2[3][1] = fma2(a3, wy, acc2[3][1]);
            acc2[3][2] = fma2(a3, wz, acc2[3][2]);
            acc2[3][3] = fma2(a3, ww, acc2[3][3]);
            rowp += TPAD;
        }

        float4 bb = *(const float4*)&b2[jg * 4];
        float q0 = 0.f, q1 = 0.f, q2 = 0.f, q3 = 0.f;
#pragma unroll
        for (int p = 0; p < 4; p++) {
            bool ok0 = (base + mg * 8 + 2 * p + 0) < N;
            bool ok1 = (base + mg * 8 + 2 * p + 1) < N;
            float lo, hi;
            unpack2(acc2[p][0], lo, hi);
            if (ok0) q0 += fmaxf(lo + bb.x, 0.f);
            if (ok1) q0 += fmaxf(hi + bb.x, 0.f);
            unpack2(acc2[p][1], lo, hi);
            if (ok0) q1 += fmaxf(lo + bb.y, 0.f);
            if (ok1) q1 += fmaxf(hi + bb.y, 0.f);
            unpack2(acc2[p][2], lo, hi);
            if (ok0) q2 += fmaxf(lo + bb.z, 0.f);
            if (ok1) q2 += fmaxf(hi + bb.z, 0.f);
            unpack2(acc2[p][3], lo, hi);
            if (ok0) q3 += fmaxf(lo + bb.w, 0.f);
            if (ok1) q3 += fmaxf(hi + bb.w, 0.f);
        }
        atomicAdd(&s_ge[jg * 4 + 0], q0);
        atomicAdd(&s_ge[jg * 4 + 1], q1);
        atomicAdd(&s_ge[jg * 4 + 2], q2);
        atomicAdd(&s_ge[jg * 4 + 3], q3);
        __syncthreads();
        atomicAdd(&g_ge[t], s_ge[t]);
    }

    // ---- arrival counter ----
    __threadfence();
    if (t == 0) {
        int c = atomicAdd(&g_done, 1);
        s_last = (c == (int)gridDim.x - 1);
    }
    __syncthreads();
    if (!s_last) return;

    // ---- final MLP (single block) ----
    __shared__ float f_ge[256];
    __shared__ float f_m[128];
    float ge = g_ge[t];
    f_ge[t] = ge;
    out[t] = ge;
    __syncthreads();
    if (t < 128) {
        float acc = bp1[t];
        for (int k = 0; k < 256; k++)
            acc = fmaf(f_ge[k], __ldg(&Wp1[k * 128 + t]), acc);
        f_m[t] = fmaxf(acc, 0.0f) * __ldg(&Wp2[t]);
    }
    __syncthreads();
    for (int off = 64; off >= 1; off >>= 1) {
        if (t < off) f_m[t] += f_m[t + off];
        __syncthreads();
    }
    if (t == 0) out[256] = f_m[0] + bp2[0];

    // ---- re-zero degree counts for the next replay ----
    for (int i = t; i < MAXN; i += 256) {
        g_incnt[i] = 0;
        g_outcnt[i] = 0;
    }
}

// ---------------------------------------------------------------------------
extern "C" void kernel_launch(void* const* d_in, const int* in_sizes, int n_in,
                              void* d_out, int out_size) {
    const float* W1  = (const float*)d_in[0];
    const float* b1  = (const float*)d_in[1];
    const float* W2  = (const float*)d_in[2];
    const float* b2  = (const float*)d_in[3];
    const float* Wp1 = (const float*)d_in[4];
    const float* bp1 = (const float*)d_in[5];
    const float* Wp2 = (const float*)d_in[6];
    const float* bp2 = (const float*)d_in[7];
    const int*   src = (const int*)d_in[8];
    const int*   dst = (const int*)d_in[9];
    const int*   np  = (n_in > 10) ? (const int*)d_in[10] : nullptr;
    int E = in_sizes[8];

    int eb  = (E + NTHREADS - 1) / NTHREADS;
    int eb2 = (E / 2 + NTHREADS - 1) / NTHREADS + 1;
    k_count<<<eb2, NTHREADS>>>(src, dst, E);
    k_scan<<<1, 1024>>>();
    k_fill<<<eb, NTHREADS>>>(src, dst, E);
    k_aggpair<<<(MAXN * 32 + NTHREADS - 1) / NTHREADS, NTHREADS>>>(np);
    k_agg2<<<(MAXN * 32 + NTHREADS - 1) / NTHREADS, NTHREADS>>>(W1, b1, np);
    k_h2sum<<<H2_GRID, NTHREADS>>>(W2, b2, Wp1, bp1, Wp2, bp2, (float*)d_out, np);
    (void)out_size; (void)n_in;
}